// round 6
// baseline (speedup 1.0000x reference)
#include <cuda_runtime.h>
#include <cuda_bf16.h>
#include <mma.h>
#include <cstdint>
#include <math.h>

using namespace nvcuda;

#define BATCH    4
#define N_TOK    16384
#define D        192
#define DFF      768
#define HEADS    6
#define DH       32
#define M_CL     64
#define KC       (N_TOK / M_CL)
#define BN_ROWS  (BATCH * N_TOK)     // 65536
#define GRID_W   128

typedef __nv_bfloat16 bf16;

// ---------------- scratch (static device globals; no allocations) ----------
__device__ bf16  g_xn  [BN_ROWS * D];
__device__ bf16  g_qkv [BN_ROWS * 3 * D];
__device__ bf16  g_o   [BN_ROWS * D];
__device__ bf16  g_h   [BN_ROWS * DFF];
__device__ bf16  g_wqkv[2 * D * 3 * D];     // [K][N] bf16
__device__ bf16  g_wprj[2 * D * D];
__device__ bf16  g_wfc1[2 * D * DFF];
__device__ bf16  g_wfc2[2 * DFF * D];
__device__ int   g_ord[BN_ROWS];
__device__ int   g_inv[BN_ROWS];

// ---------------- helpers ----------------------------------------------------
__device__ __forceinline__ uint32_t smem_u32(const void* p) {
    uint32_t a;
    asm("{ .reg .u64 t; cvta.to.shared.u64 t, %1; cvt.u32.u64 %0, t; }"
        : "=r"(a) : "l"(p));
    return a;
}
__device__ __forceinline__ void cpasync16(uint32_t saddr, const void* g) {
    asm volatile("cp.async.cg.shared.global [%0], [%1], 16;"
                 :: "r"(saddr), "l"(g) : "memory");
}

// ---------------- fp32 -> bf16 weight conversion ----------------------------
__global__ void f2bf_kernel(const float* __restrict__ in, bf16* __restrict__ out,
                            int n) {
    int i = blockIdx.x * blockDim.x + threadIdx.x;
    if (i < n) out[i] = __float2bfloat16(in[i]);
}

// ---------------- order: keys are a permutation of 0..n-1 ------------------
__global__ void order_kernel(const float* __restrict__ pos) {
    int i = blockIdx.x * blockDim.x + threadIdx.x;
    if (i >= BN_ROWS) return;
    int b = i / N_TOK;
    int ix = (int)floorf(pos[(size_t)i * 2 + 0]);
    int iy = (int)floorf(pos[(size_t)i * 2 + 1]);
    int key = iy * GRID_W + ((iy & 1) ? (GRID_W - 1 - ix) : ix);
    int rank = b * N_TOK + key;
    g_inv[i]    = rank;
    g_ord[rank] = i;
}

// ---------------- layernorm: one warp per token, bf16 out ------------------
__global__ void ln_kernel(const float* __restrict__ x,
                          const float* __restrict__ gamma,
                          const float* __restrict__ beta,
                          bf16* __restrict__ out) {
    int warp = (blockIdx.x * blockDim.x + threadIdx.x) >> 5;
    int lane = threadIdx.x & 31;
    if (warp >= BN_ROWS) return;
    const float* xr = x + (size_t)warp * D;
    float v[6];
    float s = 0.f, s2 = 0.f;
#pragma unroll
    for (int j = 0; j < 6; j++) {
        v[j] = xr[lane + 32 * j];
        s += v[j]; s2 += v[j] * v[j];
    }
#pragma unroll
    for (int o = 16; o; o >>= 1) {
        s  += __shfl_xor_sync(0xffffffffu, s,  o);
        s2 += __shfl_xor_sync(0xffffffffu, s2, o);
    }
    float mean = s * (1.f / D);
    float var  = s2 * (1.f / D) - mean * mean;
    float rstd = rsqrtf(var + 1e-5f);
    bf16* orow = out + (size_t)warp * D;
#pragma unroll
    for (int j = 0; j < 6; j++) {
        int c = lane + 32 * j;
        orow[c] = __float2bfloat16((v[j] - mean) * rstd * gamma[c] + beta[c]);
    }
}

__device__ __forceinline__ float gelu_tanh(float v) {
    float c = v + 0.044715f * v * v * v;
    return 0.5f * v * (1.f + tanhf(0.7978845608028654f * c));
}

// ---------------- bf16 wmma GEMM, full-K smem residency ---------------------
// Block 128x64, K consumed in 192-wide chunks fully resident in smem.
// 256 threads = 8 warps (4x2), warp tile 32x32 (2x2 m16n16k16).
// cp.async tile loads; 2 barriers per chunk.
#define BM 128
#define BN 64
#define KCH 192
#define LDA 200   // bf16: 192 + 8 pad
#define LDB 72    // bf16: 64 + 8 pad
#define LDC 68    // fp32 epilogue stage
#define SM_BYTES (BM * LDA * 2 + KCH * LDB * 2)   // 51200 + 27648 = 78848

template <int ACT, bool SCATTER, bool RES, bool OUTBF>
__global__ __launch_bounds__(256) void gemm_bf(
        const bf16*  __restrict__ A,
        const bf16*  __restrict__ W,
        const float* __restrict__ bias,
        const float* __restrict__ res,
        const int*   __restrict__ omap,
        void* __restrict__ Cout,
        int K, int N) {
    extern __shared__ __align__(16) unsigned char smraw[];
    bf16*  As = (bf16*)smraw;                       // [BM][LDA]
    bf16*  Bs = (bf16*)(smraw + BM * LDA * 2);      // [KCH][LDB]
    float* Cs = (float*)smraw;                      // epilogue stage [BM][LDC]
    uint32_t sA = smem_u32(As);
    uint32_t sB = smem_u32(Bs);

    int tid  = threadIdx.x;
    int warp = tid >> 5;
    int lane = tid & 31;
    int mw   = warp >> 1;
    int nw   = warp & 1;
    int mbase = blockIdx.y * BM;
    int nbase = blockIdx.x * BN;

    wmma::fragment<wmma::accumulator, 16, 16, 16, float> acc[2][2];
#pragma unroll
    for (int i = 0; i < 2; i++)
#pragma unroll
        for (int j = 0; j < 2; j++) wmma::fill_fragment(acc[i][j], 0.f);

    const int nch = K / KCH;
    for (int kc = 0; kc < nch; kc++) {
        int k0 = kc * KCH;
        // A chunk: 128 x 192 bf16 = 3072 uint4, 12 per thread
#pragma unroll
        for (int p = 0; p < 12; p++) {
            int idx = tid + p * 256;
            int r = idx / 24;
            int c = (idx % 24) * 8;
            cpasync16(sA + (uint32_t)(r * LDA + c) * 2,
                      &A[(size_t)(mbase + r) * K + k0 + c]);
        }
        // B chunk: 192 x 64 bf16 = 1536 uint4, 6 per thread
#pragma unroll
        for (int p = 0; p < 6; p++) {
            int idx = tid + p * 256;
            int r = idx >> 3;
            int c = (idx & 7) * 8;
            cpasync16(sB + (uint32_t)(r * LDB + c) * 2,
                      &W[(size_t)(k0 + r) * N + nbase + c]);
        }
        asm volatile("cp.async.commit_group;" ::: "memory");
        asm volatile("cp.async.wait_group 0;" ::: "memory");
        __syncthreads();

#pragma unroll
        for (int kk = 0; kk < KCH; kk += 16) {
            wmma::fragment<wmma::matrix_a, 16, 16, 16, bf16, wmma::row_major> af[2];
            wmma::fragment<wmma::matrix_b, 16, 16, 16, bf16, wmma::row_major> bfr[2];
#pragma unroll
            for (int i = 0; i < 2; i++)
                wmma::load_matrix_sync(af[i], &As[(mw * 32 + 16 * i) * LDA + kk], LDA);
#pragma unroll
            for (int j = 0; j < 2; j++)
                wmma::load_matrix_sync(bfr[j], &Bs[kk * LDB + nw * 32 + 16 * j], LDB);
#pragma unroll
            for (int i = 0; i < 2; i++)
#pragma unroll
                for (int j = 0; j < 2; j++)
                    wmma::mma_sync(acc[i][j], af[i], bfr[j], acc[i][j]);
        }
        __syncthreads();
    }

    // epilogue: stage fp32 to smem (aliases As; all warps past mma loop)
#pragma unroll
    for (int i = 0; i < 2; i++)
#pragma unroll
        for (int j = 0; j < 2; j++)
            wmma::store_matrix_sync(
                &Cs[(mw * 32 + 16 * i) * LDC + nw * 32 + 16 * j],
                acc[i][j], LDC, wmma::mem_row_major);
    __syncthreads();

    for (int idx = tid; idx < BM * BN; idx += 256) {
        int r  = idx >> 6;
        int cc = idx & 63;
        float v = Cs[r * LDC + cc] + bias[nbase + cc];
        if (ACT == 1) v = gelu_tanh(v);
        int orow = SCATTER ? omap[mbase + r] : (mbase + r);
        if (RES) v += res[(size_t)orow * N + nbase + cc];
        if (OUTBF)
            ((bf16*)Cout)[(size_t)orow * N + nbase + cc] = __float2bfloat16(v);
        else
            ((float*)Cout)[(size_t)orow * N + nbase + cc] = v;
    }
}

// ---------------- cluster attention: flash-style, bf16 I/O -----------------
__global__ void attn_kernel(const bf16* __restrict__ qkv,
                            bf16* __restrict__ o) {
    int hidx = blockIdx.x % HEADS;
    int rem  = blockIdx.x / HEADS;
    int c    = rem % KC;
    int b    = rem / KC;
    int i    = threadIdx.x;

    __shared__ uint4 Ks[M_CL][4];
    __shared__ uint4 Vs[M_CL][4];

    size_t base = (size_t)(b * N_TOK + c * M_CL) * (3 * D);
    const bf16* row = qkv + base + (size_t)i * (3 * D) + hidx * DH;

    float q[DH];
#pragma unroll
    for (int t = 0; t < 4; t++) {
        uint4 qv = ((const uint4*)row)[t];
        Ks[i][t] = ((const uint4*)(row + D))[t];
        Vs[i][t] = ((const uint4*)(row + 2 * D))[t];
        const __nv_bfloat162* h2 = (const __nv_bfloat162*)&qv;
#pragma unroll
        for (int e = 0; e < 4; e++) {
            float2 f = __bfloat1622float2(h2[e]);
            q[t * 8 + 2 * e + 0] = f.x;
            q[t * 8 + 2 * e + 1] = f.y;
        }
    }
    __syncthreads();

    const float scale = 0.17677669529663687f;
    float acc[DH];
#pragma unroll
    for (int d = 0; d < DH; d++) acc[d] = 0.f;
    float sum = 0.f;

#pragma unroll 2
    for (int j = 0; j < M_CL; j++) {
        float s = 0.f;
#pragma unroll
        for (int t = 0; t < 4; t++) {
            uint4 kv = Ks[j][t];
            const __nv_bfloat162* h2 = (const __nv_bfloat162*)&kv;
#pragma unroll
            for (int e = 0; e < 4; e++) {
                float2 f = __bfloat1622float2(h2[e]);
                s += q[t * 8 + 2 * e] * f.x + q[t * 8 + 2 * e + 1] * f.y;
            }
        }
        float p = __expf(s * scale);
        sum += p;
#pragma unroll
        for (int t = 0; t < 4; t++) {
            uint4 vv = Vs[j][t];
            const __nv_bfloat162* h2 = (const __nv_bfloat162*)&vv;
#pragma unroll
            for (int e = 0; e < 4; e++) {
                float2 f = __bfloat1622float2(h2[e]);
                acc[t * 8 + 2 * e + 0] += p * f.x;
                acc[t * 8 + 2 * e + 1] += p * f.y;
            }
        }
    }
    float inv = 1.f / sum;
    int tok = g_ord[b * N_TOK + c * M_CL + i];
    bf16* orow = o + (size_t)tok * D + hidx * DH;
#pragma unroll
    for (int d = 0; d < DH; d++) orow[d] = __float2bfloat16(acc[d] * inv);
}

// ---------------- launch ----------------------------------------------------
extern "C" void kernel_launch(void* const* d_in, const int* in_sizes, int n_in,
                              void* d_out, int out_size) {
    const float* x      = (const float*)d_in[0];
    const float* pos    = (const float*)d_in[1];
    const float* ln1_g  = (const float*)d_in[2];
    const float* ln1_b  = (const float*)d_in[3];
    const float* w_qkv  = (const float*)d_in[4];
    const float* b_qkv  = (const float*)d_in[5];
    const float* w_proj = (const float*)d_in[6];
    const float* b_proj = (const float*)d_in[7];
    const float* ln2_g  = (const float*)d_in[8];
    const float* ln2_b  = (const float*)d_in[9];
    const float* w_fc1  = (const float*)d_in[10];
    const float* b_fc1  = (const float*)d_in[11];
    const float* w_fc2  = (const float*)d_in[12];
    const float* b_fc2  = (const float*)d_in[13];
    float* out = (float*)d_out;

    bf16 *xn, *qkv, *o, *hbuf, *wqkv, *wprj, *wfc1, *wfc2;
    int *inv;
    cudaGetSymbolAddress((void**)&xn,   g_xn);
    cudaGetSymbolAddress((void**)&qkv,  g_qkv);
    cudaGetSymbolAddress((void**)&o,    g_o);
    cudaGetSymbolAddress((void**)&hbuf, g_h);
    cudaGetSymbolAddress((void**)&wqkv, g_wqkv);
    cudaGetSymbolAddress((void**)&wprj, g_wprj);
    cudaGetSymbolAddress((void**)&wfc1, g_wfc1);
    cudaGetSymbolAddress((void**)&wfc2, g_wfc2);
    cudaGetSymbolAddress((void**)&inv,  g_inv);

    cudaFuncSetAttribute(gemm_bf<0, true,  false, true >,
        cudaFuncAttributeMaxDynamicSharedMemorySize, SM_BYTES);
    cudaFuncSetAttribute(gemm_bf<0, false, true,  false>,
        cudaFuncAttributeMaxDynamicSharedMemorySize, SM_BYTES);
    cudaFuncSetAttribute(gemm_bf<1, false, false, true >,
        cudaFuncAttributeMaxDynamicSharedMemorySize, SM_BYTES);

    cudaMemcpyAsync(out, x, sizeof(float) * (size_t)BN_ROWS * D,
                    cudaMemcpyDeviceToDevice, 0);

    f2bf_kernel<<<(2 * D * 3 * D + 255) / 256, 256>>>(w_qkv,  wqkv, 2 * D * 3 * D);
    f2bf_kernel<<<(2 * D * D     + 255) / 256, 256>>>(w_proj, wprj, 2 * D * D);
    f2bf_kernel<<<(2 * D * DFF   + 255) / 256, 256>>>(w_fc1,  wfc1, 2 * D * DFF);
    f2bf_kernel<<<(2 * DFF * D   + 255) / 256, 256>>>(w_fc2,  wfc2, 2 * DFF * D);

    order_kernel<<<BN_ROWS / 256, 256>>>(pos);

    dim3 gQKV(3 * D / BN, BN_ROWS / BM);   // (9, 512)
    dim3 gPRJ(D / BN,     BN_ROWS / BM);   // (3, 512)
    dim3 gFC1(DFF / BN,   BN_ROWS / BM);   // (12, 512)
    dim3 gFC2(D / BN,     BN_ROWS / BM);   // (3, 512)
    int lnBlocks = BN_ROWS / 8;

    for (int i = 0; i < 2; i++) {
        // attention branch
        ln_kernel<<<lnBlocks, 256>>>(out, ln1_g + i * D, ln1_b + i * D, xn);
        gemm_bf<0, true, false, true><<<gQKV, 256, SM_BYTES>>>(
            xn, wqkv + (size_t)i * D * 3 * D, b_qkv + i * 3 * D,
            nullptr, inv, qkv, D, 3 * D);
        attn_kernel<<<BATCH * KC * HEADS, M_CL>>>(qkv, o);
        gemm_bf<0, false, true, false><<<gPRJ, 256, SM_BYTES>>>(
            o, wprj + (size_t)i * D * D, b_proj + i * D,
            out, nullptr, out, D, D);
        // MLP branch
        ln_kernel<<<lnBlocks, 256>>>(out, ln2_g + i * D, ln2_b + i * D, xn);
        gemm_bf<1, false, false, true><<<gFC1, 256, SM_BYTES>>>(
            xn, wfc1 + (size_t)i * D * DFF, b_fc1 + i * DFF,
            nullptr, nullptr, hbuf, D, DFF);
        gemm_bf<0, false, true, false><<<gFC2, 256, SM_BYTES>>>(
            hbuf, wfc2 + (size_t)i * DFF * D, b_fc2 + i * D,
            out, nullptr, out, DFF, D);
    }
}

// round 7
// speedup vs baseline: 1.3617x; 1.3617x over previous
#include <cuda_runtime.h>
#include <cuda_bf16.h>
#include <cstdint>
#include <math.h>

#define BATCH    4
#define N_TOK    16384
#define D        192
#define DFF      768
#define HEADS    6
#define DH       32
#define M_CL     64
#define KC       (N_TOK / M_CL)
#define BN_ROWS  (BATCH * N_TOK)     // 65536
#define GRID_W   128

typedef __nv_bfloat16 bf16;

// ---------------- scratch ----------------------------------------------------
__device__ bf16  g_xn  [BN_ROWS * D];
__device__ bf16  g_qkv [BN_ROWS * 3 * D];
__device__ bf16  g_o   [BN_ROWS * D];
__device__ bf16  g_h   [BN_ROWS * DFF];
__device__ bf16  g_wqkv[2 * D * 3 * D];     // [K][N] bf16
__device__ bf16  g_wprj[2 * D * D];
__device__ bf16  g_wfc1[2 * D * DFF];
__device__ bf16  g_wfc2[2 * DFF * D];
__device__ int   g_ord[BN_ROWS];
__device__ int   g_inv[BN_ROWS];

// ---------------- helpers ----------------------------------------------------
__device__ __forceinline__ uint32_t smem_u32(const void* p) {
    uint32_t a;
    asm("{ .reg .u64 t; cvta.to.shared.u64 t, %1; cvt.u32.u64 %0, t; }"
        : "=r"(a) : "l"(p));
    return a;
}
__device__ __forceinline__ void cpasync16(uint32_t saddr, const void* g) {
    asm volatile("cp.async.cg.shared.global [%0], [%1], 16;"
                 :: "r"(saddr), "l"(g) : "memory");
}
__device__ __forceinline__ void ldsm_x4(uint32_t* r, uint32_t addr) {
    asm volatile("ldmatrix.sync.aligned.m8n8.x4.shared.b16 {%0,%1,%2,%3}, [%4];"
                 : "=r"(r[0]), "=r"(r[1]), "=r"(r[2]), "=r"(r[3]) : "r"(addr));
}
__device__ __forceinline__ void ldsm_x4t(uint32_t* r, uint32_t addr) {
    asm volatile("ldmatrix.sync.aligned.m8n8.x4.trans.shared.b16 {%0,%1,%2,%3}, [%4];"
                 : "=r"(r[0]), "=r"(r[1]), "=r"(r[2]), "=r"(r[3]) : "r"(addr));
}
__device__ __forceinline__ void mma16816(float* c, const uint32_t* a,
                                         const uint32_t* b) {
    asm volatile(
        "mma.sync.aligned.m16n8k16.row.col.f32.bf16.bf16.f32 "
        "{%0,%1,%2,%3}, {%4,%5,%6,%7}, {%8,%9}, {%0,%1,%2,%3};"
        : "+f"(c[0]), "+f"(c[1]), "+f"(c[2]), "+f"(c[3])
        : "r"(a[0]), "r"(a[1]), "r"(a[2]), "r"(a[3]), "r"(b[0]), "r"(b[1]));
}

// ---------------- fused weight prep (single launch) -------------------------
#define SZ_QKV (2 * D * 3 * D)
#define SZ_PRJ (2 * D * D)
#define SZ_FC1 (2 * D * DFF)
#define SZ_FC2 (2 * DFF * D)
__global__ void wprep_kernel(const float* __restrict__ wq, const float* __restrict__ wp,
                             const float* __restrict__ w1, const float* __restrict__ w2) {
    int i = blockIdx.x * blockDim.x + threadIdx.x;
    if (i < SZ_QKV) g_wqkv[i] = __float2bfloat16(wq[i]);
    if (i < SZ_PRJ) g_wprj[i] = __float2bfloat16(wp[i]);
    if (i < SZ_FC1) g_wfc1[i] = __float2bfloat16(w1[i]);
    if (i < SZ_FC2) g_wfc2[i] = __float2bfloat16(w2[i]);
}

// ---------------- order ------------------------------------------------------
__global__ void order_kernel(const float* __restrict__ pos) {
    int i = blockIdx.x * blockDim.x + threadIdx.x;
    if (i >= BN_ROWS) return;
    int b = i / N_TOK;
    int ix = (int)floorf(pos[(size_t)i * 2 + 0]);
    int iy = (int)floorf(pos[(size_t)i * 2 + 1]);
    int key = iy * GRID_W + ((iy & 1) ? (GRID_W - 1 - ix) : ix);
    int rank = b * N_TOK + key;
    g_inv[i]    = rank;
    g_ord[rank] = i;
}

// ---------------- layernorm --------------------------------------------------
__global__ void ln_kernel(const float* __restrict__ x,
                          const float* __restrict__ gamma,
                          const float* __restrict__ beta,
                          bf16* __restrict__ out) {
    int warp = (blockIdx.x * blockDim.x + threadIdx.x) >> 5;
    int lane = threadIdx.x & 31;
    if (warp >= BN_ROWS) return;
    const float* xr = x + (size_t)warp * D;
    float v[6];
    float s = 0.f, s2 = 0.f;
#pragma unroll
    for (int j = 0; j < 6; j++) {
        v[j] = xr[lane + 32 * j];
        s += v[j]; s2 += v[j] * v[j];
    }
#pragma unroll
    for (int o = 16; o; o >>= 1) {
        s  += __shfl_xor_sync(0xffffffffu, s,  o);
        s2 += __shfl_xor_sync(0xffffffffu, s2, o);
    }
    float mean = s * (1.f / D);
    float var  = s2 * (1.f / D) - mean * mean;
    float rstd = rsqrtf(var + 1e-5f);
    bf16* orow = out + (size_t)warp * D;
#pragma unroll
    for (int j = 0; j < 6; j++) {
        int c = lane + 32 * j;
        orow[c] = __float2bfloat16((v[j] - mean) * rstd * gamma[c] + beta[c]);
    }
}

__device__ __forceinline__ float gelu_tanh(float v) {
    float c = v + 0.044715f * v * v * v;
    return 0.5f * v * (1.f + tanhf(0.7978845608028654f * c));
}

// ---------------- raw mma.sync GEMM ------------------------------------------
// Block 128x64, 4 warps (2x2), warp tile 64x32. BK=64, 2-stage cp.async.
// A: [M][K] bf16 row-major. W: [K][N] bf16 row-major.
#define BMm   128
#define BNm   64
#define BKm   64
#define LDAS  72                        // A stage row stride (elements)
#define LDBS  72                        // B stage row stride
#define AST   (BMm * LDAS)              // 9216 elem
#define BST   (BKm * LDBS)              // 4608 elem
#define STAGE (AST + BST)               // 13824 elem = 27648 B
#define SMEMB (2 * STAGE * 2)           // 55296 B

template <int ACT, bool SCATTER, bool RES, bool OUTBF>
__global__ __launch_bounds__(128) void gemm_mma(
        const bf16*  __restrict__ A,
        const bf16*  __restrict__ W,
        const float* __restrict__ bias,
        const float* __restrict__ res,
        const int*   __restrict__ omap,
        void* __restrict__ Cout,
        int K, int N) {
    extern __shared__ __align__(16) bf16 sm[];
    uint32_t sbase = smem_u32(sm);

    int tid   = threadIdx.x;
    int wid   = tid >> 5;
    int lane  = tid & 31;
    int warpM = wid >> 1;          // 0,1 -> M offset 64
    int warpN = wid & 1;           // 0,1 -> N offset 32
    int mbase = blockIdx.y * BMm;
    int nbase = blockIdx.x * BNm;

    float c[4][4][4];
#pragma unroll
    for (int mi = 0; mi < 4; mi++)
#pragma unroll
        for (int ni = 0; ni < 4; ni++)
#pragma unroll
            for (int e = 0; e < 4; e++) c[mi][ni][e] = 0.f;

    // per-lane ldmatrix offsets (elements)
    int aRow  = warpM * 64 + (lane & 15);
    int aKad  = (lane >> 4) << 3;
    int bKad  = ((lane >> 3) & 1) * 8 + (lane & 7);
    int bNad  = warpN * 32 + ((lane >> 4) << 3);

    const int nch = K / BKm;

    // ---- stage loaders ----
    auto load_stage = [&](int st, int k0) {
        uint32_t sA = sbase + (uint32_t)(st * STAGE) * 2;
        uint32_t sB = sA + (uint32_t)AST * 2;
#pragma unroll
        for (int p = 0; p < 8; p++) {           // A: 128x64 = 1024 uint4
            int idx = tid + p * 128;
            int r = idx >> 3, cc = (idx & 7) * 8;
            cpasync16(sA + (uint32_t)(r * LDAS + cc) * 2,
                      &A[(size_t)(mbase + r) * K + k0 + cc]);
        }
#pragma unroll
        for (int p = 0; p < 4; p++) {           // B: 64x64 = 512 uint4
            int idx = tid + p * 128;
            int r = idx >> 3, cc = (idx & 7) * 8;
            cpasync16(sB + (uint32_t)(r * LDBS + cc) * 2,
                      &W[(size_t)(k0 + r) * N + nbase + cc]);
        }
        asm volatile("cp.async.commit_group;" ::: "memory");
    };

    load_stage(0, 0);
    for (int kc = 0; kc < nch; kc++) {
        if (kc + 1 < nch) load_stage((kc + 1) & 1, (kc + 1) * BKm);
        if (kc + 1 < nch)
            asm volatile("cp.async.wait_group 1;" ::: "memory");
        else
            asm volatile("cp.async.wait_group 0;" ::: "memory");
        __syncthreads();

        uint32_t sA = sbase + (uint32_t)((kc & 1) * STAGE) * 2;
        uint32_t sB = sA + (uint32_t)AST * 2;
#pragma unroll
        for (int kk = 0; kk < BKm; kk += 16) {
            uint32_t af[4][4], bfr[2][4];
#pragma unroll
            for (int mi = 0; mi < 4; mi++)
                ldsm_x4(af[mi],
                    sA + (uint32_t)((aRow + mi * 16) * LDAS + kk + aKad) * 2);
#pragma unroll
            for (int nh = 0; nh < 2; nh++)
                ldsm_x4t(bfr[nh],
                    sB + (uint32_t)((kk + bKad) * LDBS + bNad + nh * 16) * 2);
#pragma unroll
            for (int mi = 0; mi < 4; mi++)
#pragma unroll
                for (int ni = 0; ni < 4; ni++)
                    mma16816(c[mi][ni], af[mi], &bfr[ni >> 1][(ni & 1) * 2]);
        }
        __syncthreads();
    }

    // ---- epilogue: direct from fragments ----
    int grp = lane >> 2;
    int qid = lane & 3;
#pragma unroll
    for (int mi = 0; mi < 4; mi++) {
#pragma unroll
        for (int ni = 0; ni < 4; ni++) {
            int col = nbase + warpN * 32 + ni * 8 + qid * 2;
            float b0 = bias[col], b1 = bias[col + 1];
#pragma unroll
            for (int half = 0; half < 2; half++) {
                int row = mbase + warpM * 64 + mi * 16 + grp + half * 8;
                int orow = SCATTER ? omap[row] : row;
                float v0 = c[mi][ni][half * 2 + 0] + b0;
                float v1 = c[mi][ni][half * 2 + 1] + b1;
                if (ACT == 1) { v0 = gelu_tanh(v0); v1 = gelu_tanh(v1); }
                if (RES) {
                    const float2 r2 = *(const float2*)&res[(size_t)orow * N + col];
                    v0 += r2.x; v1 += r2.y;
                }
                if (OUTBF) {
                    __nv_bfloat162 pk;
                    pk.x = __float2bfloat16(v0);
                    pk.y = __float2bfloat16(v1);
                    *(__nv_bfloat162*)&((bf16*)Cout)[(size_t)orow * N + col] = pk;
                } else {
                    float2 o2; o2.x = v0; o2.y = v1;
                    *(float2*)&((float*)Cout)[(size_t)orow * N + col] = o2;
                }
            }
        }
    }
}

// ---------------- cluster attention ------------------------------------------
__global__ void attn_kernel(const bf16* __restrict__ qkv,
                            bf16* __restrict__ o) {
    int hidx = blockIdx.x % HEADS;
    int rem  = blockIdx.x / HEADS;
    int c    = rem % KC;
    int b    = rem / KC;
    int i    = threadIdx.x;

    __shared__ uint4 Ks[M_CL][4];
    __shared__ uint4 Vs[M_CL][4];

    size_t base = (size_t)(b * N_TOK + c * M_CL) * (3 * D);
    const bf16* row = qkv + base + (size_t)i * (3 * D) + hidx * DH;

    float q[DH];
#pragma unroll
    for (int t = 0; t < 4; t++) {
        uint4 qv = ((const uint4*)row)[t];
        Ks[i][t] = ((const uint4*)(row + D))[t];
        Vs[i][t] = ((const uint4*)(row + 2 * D))[t];
        const __nv_bfloat162* h2 = (const __nv_bfloat162*)&qv;
#pragma unroll
        for (int e = 0; e < 4; e++) {
            float2 f = __bfloat1622float2(h2[e]);
            q[t * 8 + 2 * e + 0] = f.x;
            q[t * 8 + 2 * e + 1] = f.y;
        }
    }
    __syncthreads();

    const float scale = 0.17677669529663687f;
    float acc[DH];
#pragma unroll
    for (int d = 0; d < DH; d++) acc[d] = 0.f;
    float sum = 0.f;

#pragma unroll 2
    for (int j = 0; j < M_CL; j++) {
        float s = 0.f;
#pragma unroll
        for (int t = 0; t < 4; t++) {
            uint4 kv = Ks[j][t];
            const __nv_bfloat162* h2 = (const __nv_bfloat162*)&kv;
#pragma unroll
            for (int e = 0; e < 4; e++) {
                float2 f = __bfloat1622float2(h2[e]);
                s += q[t * 8 + 2 * e] * f.x + q[t * 8 + 2 * e + 1] * f.y;
            }
        }
        float p = __expf(s * scale);
        sum += p;
#pragma unroll
        for (int t = 0; t < 4; t++) {
            uint4 vv = Vs[j][t];
            const __nv_bfloat162* h2 = (const __nv_bfloat162*)&vv;
#pragma unroll
            for (int e = 0; e < 4; e++) {
                float2 f = __bfloat1622float2(h2[e]);
                acc[t * 8 + 2 * e + 0] += p * f.x;
                acc[t * 8 + 2 * e + 1] += p * f.y;
            }
        }
    }
    float inv = 1.f / sum;
    int tok = g_ord[b * N_TOK + c * M_CL + i];
    bf16* orow = o + (size_t)tok * D + hidx * DH;
#pragma unroll
    for (int d = 0; d < DH; d++) orow[d] = __float2bfloat16(acc[d] * inv);
}

// ---------------- launch ------------------------------------------------------
extern "C" void kernel_launch(void* const* d_in, const int* in_sizes, int n_in,
                              void* d_out, int out_size) {
    const float* x      = (const float*)d_in[0];
    const float* pos    = (const float*)d_in[1];
    const float* ln1_g  = (const float*)d_in[2];
    const float* ln1_b  = (const float*)d_in[3];
    const float* w_qkv  = (const float*)d_in[4];
    const float* b_qkv  = (const float*)d_in[5];
    const float* w_proj = (const float*)d_in[6];
    const float* b_proj = (const float*)d_in[7];
    const float* ln2_g  = (const float*)d_in[8];
    const float* ln2_b  = (const float*)d_in[9];
    const float* w_fc1  = (const float*)d_in[10];
    const float* b_fc1  = (const float*)d_in[11];
    const float* w_fc2  = (const float*)d_in[12];
    const float* b_fc2  = (const float*)d_in[13];
    float* out = (float*)d_out;

    bf16 *xn, *qkv, *o, *hbuf, *wqkv, *wprj, *wfc1, *wfc2;
    int *inv;
    cudaGetSymbolAddress((void**)&xn,   g_xn);
    cudaGetSymbolAddress((void**)&qkv,  g_qkv);
    cudaGetSymbolAddress((void**)&o,    g_o);
    cudaGetSymbolAddress((void**)&hbuf, g_h);
    cudaGetSymbolAddress((void**)&wqkv, g_wqkv);
    cudaGetSymbolAddress((void**)&wprj, g_wprj);
    cudaGetSymbolAddress((void**)&wfc1, g_wfc1);
    cudaGetSymbolAddress((void**)&wfc2, g_wfc2);
    cudaGetSymbolAddress((void**)&inv,  g_inv);

    cudaFuncSetAttribute(gemm_mma<0, true,  false, true >,
        cudaFuncAttributeMaxDynamicSharedMemorySize, SMEMB);
    cudaFuncSetAttribute(gemm_mma<0, false, true,  false>,
        cudaFuncAttributeMaxDynamicSharedMemorySize, SMEMB);
    cudaFuncSetAttribute(gemm_mma<1, false, false, true >,
        cudaFuncAttributeMaxDynamicSharedMemorySize, SMEMB);

    // launch order chosen so gemm_mma(QKV) is the 5th launch => ncu capture
    cudaMemcpyAsync(out, x, sizeof(float) * (size_t)BN_ROWS * D,
                    cudaMemcpyDeviceToDevice, 0);                       // 1
    wprep_kernel<<<(SZ_FC1 + 255) / 256, 256>>>(w_qkv, w_proj, w_fc1, w_fc2); // 2
    order_kernel<<<BN_ROWS / 256, 256>>>(pos);                          // 3

    dim3 gQKV(3 * D / BNm, BN_ROWS / BMm);   // (9, 512)
    dim3 gPRJ(D / BNm,     BN_ROWS / BMm);   // (3, 512)
    dim3 gFC1(DFF / BNm,   BN_ROWS / BMm);   // (12, 512)
    dim3 gFC2(D / BNm,     BN_ROWS / BMm);   // (3, 512)
    int lnBlocks = BN_ROWS / 8;

    for (int i = 0; i < 2; i++) {
        ln_kernel<<<lnBlocks, 256>>>(out, ln1_g + i * D, ln1_b + i * D, xn); // 4
        gemm_mma<0, true, false, true><<<gQKV, 128, SMEMB>>>(                // 5 <- capture
            xn, wqkv + (size_t)i * D * 3 * D, b_qkv + i * 3 * D,
            nullptr, inv, qkv, D, 3 * D);
        attn_kernel<<<BATCH * KC * HEADS, M_CL>>>(qkv, o);
        gemm_mma<0, false, true, false><<<gPRJ, 128, SMEMB>>>(
            o, wprj + (size_t)i * D * D, b_proj + i * D,
            out, nullptr, out, D, D);
        ln_kernel<<<lnBlocks, 256>>>(out, ln2_g + i * D, ln2_b + i * D, xn);
        gemm_mma<1, false, false, true><<<gFC1, 128, SMEMB>>>(
            xn, wfc1 + (size_t)i * D * DFF, b_fc1 + i * DFF,
            nullptr, nullptr, hbuf, D, DFF);
        gemm_mma<0, false, true, false><<<gFC2, 128, SMEMB>>>(
            hbuf, wfc2 + (size_t)i * DFF * D, b_fc2 + i * D,
            out, nullptr, out, DFF, D);
    }
}

// round 8
// speedup vs baseline: 2.2284x; 1.6365x over previous
#include <cuda_runtime.h>
#include <cuda_bf16.h>
#include <cstdint>
#include <math.h>

#define BATCH    4
#define N_TOK    16384
#define D        192
#define DFF      768
#define HEADS    6
#define DH       32
#define M_CL     64
#define KC       (N_TOK / M_CL)
#define BN_ROWS  (BATCH * N_TOK)     // 65536
#define GRID_W   128

typedef __nv_bfloat16 bf16;

// ---------------- scratch ----------------------------------------------------
__device__ bf16  g_xn  [BN_ROWS * D];
__device__ bf16  g_qkv [BN_ROWS * 3 * D];
__device__ bf16  g_o   [BN_ROWS * D];
__device__ bf16  g_h   [BN_ROWS * DFF];
__device__ bf16  g_wqkv[2 * D * 3 * D];     // [K][N] bf16
__device__ bf16  g_wprj[2 * D * D];
__device__ bf16  g_wfc1[2 * D * DFF];
__device__ bf16  g_wfc2[2 * DFF * D];
__device__ int   g_ord[BN_ROWS];
__device__ int   g_inv[BN_ROWS];

// ---------------- helpers ----------------------------------------------------
__device__ __forceinline__ uint32_t smem_u32(const void* p) {
    uint32_t a;
    asm("{ .reg .u64 t; cvta.to.shared.u64 t, %1; cvt.u32.u64 %0, t; }"
        : "=r"(a) : "l"(p));
    return a;
}
__device__ __forceinline__ void cpasync16(uint32_t saddr, const void* g) {
    asm volatile("cp.async.cg.shared.global [%0], [%1], 16;"
                 :: "r"(saddr), "l"(g) : "memory");
}
__device__ __forceinline__ void ldsm_x4(uint32_t* r, uint32_t addr) {
    asm volatile("ldmatrix.sync.aligned.m8n8.x4.shared.b16 {%0,%1,%2,%3}, [%4];"
                 : "=r"(r[0]), "=r"(r[1]), "=r"(r[2]), "=r"(r[3]) : "r"(addr));
}
__device__ __forceinline__ void ldsm_x4t(uint32_t* r, uint32_t addr) {
    asm volatile("ldmatrix.sync.aligned.m8n8.x4.trans.shared.b16 {%0,%1,%2,%3}, [%4];"
                 : "=r"(r[0]), "=r"(r[1]), "=r"(r[2]), "=r"(r[3]) : "r"(addr));
}
__device__ __forceinline__ void mma16816(float* c, const uint32_t* a,
                                         const uint32_t* b) {
    asm volatile(
        "mma.sync.aligned.m16n8k16.row.col.f32.bf16.bf16.f32 "
        "{%0,%1,%2,%3}, {%4,%5,%6,%7}, {%8,%9}, {%0,%1,%2,%3};"
        : "+f"(c[0]), "+f"(c[1]), "+f"(c[2]), "+f"(c[3])
        : "r"(a[0]), "r"(a[1]), "r"(a[2]), "r"(a[3]), "r"(b[0]), "r"(b[1]));
}
__device__ __forceinline__ uint32_t packbf2(float lo, float hi) {
    __nv_bfloat162 pk;
    pk.x = __float2bfloat16(lo);
    pk.y = __float2bfloat16(hi);
    return *(uint32_t*)&pk;
}

// ---------------- fused prep: weights->bf16 + curve order -------------------
#define SZ_QKV (2 * D * 3 * D)
#define SZ_PRJ (2 * D * D)
#define SZ_FC1 (2 * D * DFF)
#define SZ_FC2 (2 * DFF * D)
__global__ void prep_kernel(const float* __restrict__ wq, const float* __restrict__ wp,
                            const float* __restrict__ w1, const float* __restrict__ w2,
                            const float* __restrict__ pos) {
    int i = blockIdx.x * blockDim.x + threadIdx.x;
    if (i < SZ_QKV) g_wqkv[i] = __float2bfloat16(wq[i]);
    if (i < SZ_PRJ) g_wprj[i] = __float2bfloat16(wp[i]);
    if (i < SZ_FC1) g_wfc1[i] = __float2bfloat16(w1[i]);
    if (i < SZ_FC2) g_wfc2[i] = __float2bfloat16(w2[i]);
    if (i < BN_ROWS) {
        int b = i / N_TOK;
        int ix = (int)floorf(pos[(size_t)i * 2 + 0]);
        int iy = (int)floorf(pos[(size_t)i * 2 + 1]);
        int key = iy * GRID_W + ((iy & 1) ? (GRID_W - 1 - ix) : ix);
        int rank = b * N_TOK + key;
        g_inv[i]    = rank;
        g_ord[rank] = i;
    }
}

// ---------------- layernorm --------------------------------------------------
__global__ void ln_kernel(const float* __restrict__ x,
                          const float* __restrict__ gamma,
                          const float* __restrict__ beta,
                          bf16* __restrict__ out) {
    int warp = (blockIdx.x * blockDim.x + threadIdx.x) >> 5;
    int lane = threadIdx.x & 31;
    if (warp >= BN_ROWS) return;
    const float* xr = x + (size_t)warp * D;
    float v[6];
    float s = 0.f, s2 = 0.f;
#pragma unroll
    for (int j = 0; j < 6; j++) {
        v[j] = xr[lane + 32 * j];
        s += v[j]; s2 += v[j] * v[j];
    }
#pragma unroll
    for (int o = 16; o; o >>= 1) {
        s  += __shfl_xor_sync(0xffffffffu, s,  o);
        s2 += __shfl_xor_sync(0xffffffffu, s2, o);
    }
    float mean = s * (1.f / D);
    float var  = s2 * (1.f / D) - mean * mean;
    float rstd = rsqrtf(var + 1e-5f);
    bf16* orow = out + (size_t)warp * D;
#pragma unroll
    for (int j = 0; j < 6; j++) {
        int c = lane + 32 * j;
        orow[c] = __float2bfloat16((v[j] - mean) * rstd * gamma[c] + beta[c]);
    }
}

__device__ __forceinline__ float gelu_tanh(float v) {
    float c = v + 0.044715f * v * v * v;
    return 0.5f * v * (1.f + tanhf(0.7978845608028654f * c));
}

// ---------------- raw mma.sync GEMM (unchanged from R7) ----------------------
#define BMm   128
#define BNm   64
#define BKm   64
#define LDAS  72
#define LDBS  72
#define AST   (BMm * LDAS)
#define BST   (BKm * LDBS)
#define STAGE (AST + BST)
#define SMEMB (2 * STAGE * 2)

template <int ACT, bool SCATTER, bool RES, bool OUTBF>
__global__ __launch_bounds__(128) void gemm_mma(
        const bf16*  __restrict__ A,
        const bf16*  __restrict__ W,
        const float* __restrict__ bias,
        const float* __restrict__ res,
        const int*   __restrict__ omap,
        void* __restrict__ Cout,
        int K, int N) {
    extern __shared__ __align__(16) bf16 sm[];
    uint32_t sbase = smem_u32(sm);

    int tid   = threadIdx.x;
    int wid   = tid >> 5;
    int lane  = tid & 31;
    int warpM = wid >> 1;
    int warpN = wid & 1;
    int mbase = blockIdx.y * BMm;
    int nbase = blockIdx.x * BNm;

    float c[4][4][4];
#pragma unroll
    for (int mi = 0; mi < 4; mi++)
#pragma unroll
        for (int ni = 0; ni < 4; ni++)
#pragma unroll
            for (int e = 0; e < 4; e++) c[mi][ni][e] = 0.f;

    int aRow  = warpM * 64 + (lane & 15);
    int aKad  = (lane >> 4) << 3;
    int bKad  = ((lane >> 3) & 1) * 8 + (lane & 7);
    int bNad  = warpN * 32 + ((lane >> 4) << 3);

    const int nch = K / BKm;

    auto load_stage = [&](int st, int k0) {
        uint32_t sA = sbase + (uint32_t)(st * STAGE) * 2;
        uint32_t sB = sA + (uint32_t)AST * 2;
#pragma unroll
        for (int p = 0; p < 8; p++) {
            int idx = tid + p * 128;
            int r = idx >> 3, cc = (idx & 7) * 8;
            cpasync16(sA + (uint32_t)(r * LDAS + cc) * 2,
                      &A[(size_t)(mbase + r) * K + k0 + cc]);
        }
#pragma unroll
        for (int p = 0; p < 4; p++) {
            int idx = tid + p * 128;
            int r = idx >> 3, cc = (idx & 7) * 8;
            cpasync16(sB + (uint32_t)(r * LDBS + cc) * 2,
                      &W[(size_t)(k0 + r) * N + nbase + cc]);
        }
        asm volatile("cp.async.commit_group;" ::: "memory");
    };

    load_stage(0, 0);
    for (int kc = 0; kc < nch; kc++) {
        if (kc + 1 < nch) load_stage((kc + 1) & 1, (kc + 1) * BKm);
        if (kc + 1 < nch)
            asm volatile("cp.async.wait_group 1;" ::: "memory");
        else
            asm volatile("cp.async.wait_group 0;" ::: "memory");
        __syncthreads();

        uint32_t sA = sbase + (uint32_t)((kc & 1) * STAGE) * 2;
        uint32_t sB = sA + (uint32_t)AST * 2;
#pragma unroll
        for (int kk = 0; kk < BKm; kk += 16) {
            uint32_t af[4][4], bfr[2][4];
#pragma unroll
            for (int mi = 0; mi < 4; mi++)
                ldsm_x4(af[mi],
                    sA + (uint32_t)((aRow + mi * 16) * LDAS + kk + aKad) * 2);
#pragma unroll
            for (int nh = 0; nh < 2; nh++)
                ldsm_x4t(bfr[nh],
                    sB + (uint32_t)((kk + bKad) * LDBS + bNad + nh * 16) * 2);
#pragma unroll
            for (int mi = 0; mi < 4; mi++)
#pragma unroll
                for (int ni = 0; ni < 4; ni++)
                    mma16816(c[mi][ni], af[mi], &bfr[ni >> 1][(ni & 1) * 2]);
        }
        __syncthreads();
    }

    int grp = lane >> 2;
    int qid = lane & 3;
#pragma unroll
    for (int mi = 0; mi < 4; mi++) {
#pragma unroll
        for (int ni = 0; ni < 4; ni++) {
            int col = nbase + warpN * 32 + ni * 8 + qid * 2;
            float b0 = bias[col], b1 = bias[col + 1];
#pragma unroll
            for (int half = 0; half < 2; half++) {
                int row = mbase + warpM * 64 + mi * 16 + grp + half * 8;
                int orow = SCATTER ? omap[row] : row;
                float v0 = c[mi][ni][half * 2 + 0] + b0;
                float v1 = c[mi][ni][half * 2 + 1] + b1;
                if (ACT == 1) { v0 = gelu_tanh(v0); v1 = gelu_tanh(v1); }
                if (RES) {
                    const float2 r2 = *(const float2*)&res[(size_t)orow * N + col];
                    v0 += r2.x; v1 += r2.y;
                }
                if (OUTBF) {
                    *(uint32_t*)&((bf16*)Cout)[(size_t)orow * N + col] = packbf2(v0, v1);
                } else {
                    float2 o2; o2.x = v0; o2.y = v1;
                    *(float2*)&((float*)Cout)[(size_t)orow * N + col] = o2;
                }
            }
        }
    }
}

// ---------------- tensor-core cluster attention ------------------------------
// One block per (b, cluster): 6 warps = 6 heads. qkv slab 64x576 in smem.
#define ACLS 584                       // row stride (elements), conflict-free
#define ASMB (M_CL * ACLS * 2)         // 74752 B

__global__ __launch_bounds__(192) void attn_tc(const bf16* __restrict__ qkv,
                                               bf16* __restrict__ o) {
    extern __shared__ __align__(16) bf16 sm[];
    int blk  = blockIdx.x;             // b*KC + c
    int tid  = threadIdx.x;
    int h    = tid >> 5;               // warp = head
    int lane = tid & 31;

    // load 64 x 576 bf16 slab: 4608 uint4, 24 per thread
    size_t gbase = (size_t)blk * (M_CL * 3 * D);
#pragma unroll
    for (int p = 0; p < 24; p++) {
        int idx = tid + p * 192;
        int r = idx / 72, cc = (idx % 72) * 8;
        *(uint4*)&sm[r * ACLS + cc] = *(const uint4*)&qkv[gbase + (size_t)r * 576 + cc];
    }
    __syncthreads();

    uint32_t sb    = smem_u32(sm);
    uint32_t qbse  = sb + (uint32_t)(h * 32) * 2;
    uint32_t kbse  = sb + (uint32_t)(D + h * 32) * 2;
    uint32_t vbse  = sb + (uint32_t)(2 * D + h * 32) * 2;

    // K fragments: [jb 0..3][db 0..1][4] ; non-trans ldmatrix of [n=j][k=d]
    uint32_t kb[4][2][4];
    int krow = (lane & 7) + ((lane >> 4) & 1) * 8;
    int kcol = ((lane >> 3) & 1) * 8;
#pragma unroll
    for (int jb = 0; jb < 4; jb++)
#pragma unroll
        for (int db = 0; db < 2; db++)
            ldsm_x4(kb[jb][db],
                kbse + (uint32_t)((jb * 16 + krow) * ACLS + db * 16 + kcol) * 2);

    // V fragments: trans ldmatrix of [k=j][n=d]
    uint32_t vb[4][2][4];
    int vkrow = ((lane >> 3) & 1) * 8 + (lane & 7);
    int vnad  = (lane >> 4) * 8;
#pragma unroll
    for (int jb = 0; jb < 4; jb++)
#pragma unroll
        for (int db = 0; db < 2; db++)
            ldsm_x4t(vb[jb][db],
                vbse + (uint32_t)((jb * 16 + vkrow) * ACLS + db * 16 + vnad) * 2);

    const float scale = 0.17677669529663687f;   // 1/sqrt(32)
    int arow = lane & 15, akad = (lane >> 4) << 3;
    int grp = lane >> 2;

#pragma unroll
    for (int pass = 0; pass < 4; pass++) {
        int qbase = pass * 16;
        uint32_t qa[2][4];
#pragma unroll
        for (int kg = 0; kg < 2; kg++)
            ldsm_x4(qa[kg],
                qbse + (uint32_t)((qbase + arow) * ACLS + kg * 16 + akad) * 2);

        float sacc[8][4];
#pragma unroll
        for (int nt = 0; nt < 8; nt++)
#pragma unroll
            for (int e = 0; e < 4; e++) sacc[nt][e] = 0.f;
#pragma unroll
        for (int kg = 0; kg < 2; kg++)
#pragma unroll
            for (int nt = 0; nt < 8; nt++)
                mma16816(sacc[nt], qa[kg], &kb[nt >> 1][kg][(nt & 1) * 2]);

        // exp (no max-sub; scores bounded) + row sums
        float slo = 0.f, shi = 0.f;
#pragma unroll
        for (int nt = 0; nt < 8; nt++) {
            float e0 = __expf(sacc[nt][0] * scale);
            float e1 = __expf(sacc[nt][1] * scale);
            float e2 = __expf(sacc[nt][2] * scale);
            float e3 = __expf(sacc[nt][3] * scale);
            sacc[nt][0] = e0; sacc[nt][1] = e1;
            sacc[nt][2] = e2; sacc[nt][3] = e3;
            slo += e0 + e1; shi += e2 + e3;
        }
        slo += __shfl_xor_sync(0xffffffffu, slo, 1);
        slo += __shfl_xor_sync(0xffffffffu, slo, 2);
        shi += __shfl_xor_sync(0xffffffffu, shi, 1);
        shi += __shfl_xor_sync(0xffffffffu, shi, 2);

        // pack P accums -> A fragments (C->A layout identity)
        uint32_t pa[4][4];
#pragma unroll
        for (int jb = 0; jb < 4; jb++) {
            pa[jb][0] = packbf2(sacc[2 * jb][0],     sacc[2 * jb][1]);
            pa[jb][1] = packbf2(sacc[2 * jb][2],     sacc[2 * jb][3]);
            pa[jb][2] = packbf2(sacc[2 * jb + 1][0], sacc[2 * jb + 1][1]);
            pa[jb][3] = packbf2(sacc[2 * jb + 1][2], sacc[2 * jb + 1][3]);
        }

        float oacc[4][4];
#pragma unroll
        for (int nt = 0; nt < 4; nt++)
#pragma unroll
            for (int e = 0; e < 4; e++) oacc[nt][e] = 0.f;
#pragma unroll
        for (int kg = 0; kg < 4; kg++)
#pragma unroll
            for (int nt = 0; nt < 4; nt++)
                mma16816(oacc[nt], pa[kg], &vb[kg][nt >> 1][(nt & 1) * 2]);

        float inv0 = 1.f / slo, inv1 = 1.f / shi;
        int r0 = qbase + grp;
        int tok0 = g_ord[blk * M_CL + r0];
        int tok1 = g_ord[blk * M_CL + r0 + 8];
#pragma unroll
        for (int nt = 0; nt < 4; nt++) {
            int col = h * 32 + nt * 8 + (lane & 3) * 2;
            *(uint32_t*)&o[(size_t)tok0 * D + col] =
                packbf2(oacc[nt][0] * inv0, oacc[nt][1] * inv0);
            *(uint32_t*)&o[(size_t)tok1 * D + col] =
                packbf2(oacc[nt][2] * inv1, oacc[nt][3] * inv1);
        }
    }
}

// ---------------- launch ------------------------------------------------------
extern "C" void kernel_launch(void* const* d_in, const int* in_sizes, int n_in,
                              void* d_out, int out_size) {
    const float* x      = (const float*)d_in[0];
    const float* pos    = (const float*)d_in[1];
    const float* ln1_g  = (const float*)d_in[2];
    const float* ln1_b  = (const float*)d_in[3];
    const float* w_qkv  = (const float*)d_in[4];
    const float* b_qkv  = (const float*)d_in[5];
    const float* w_proj = (const float*)d_in[6];
    const float* b_proj = (const float*)d_in[7];
    const float* ln2_g  = (const float*)d_in[8];
    const float* ln2_b  = (const float*)d_in[9];
    const float* w_fc1  = (const float*)d_in[10];
    const float* b_fc1  = (const float*)d_in[11];
    const float* w_fc2  = (const float*)d_in[12];
    const float* b_fc2  = (const float*)d_in[13];
    float* out = (float*)d_out;

    bf16 *xn, *qkv, *o, *hbuf, *wqkv, *wprj, *wfc1, *wfc2;
    int *inv;
    cudaGetSymbolAddress((void**)&xn,   g_xn);
    cudaGetSymbolAddress((void**)&qkv,  g_qkv);
    cudaGetSymbolAddress((void**)&o,    g_o);
    cudaGetSymbolAddress((void**)&hbuf, g_h);
    cudaGetSymbolAddress((void**)&wqkv, g_wqkv);
    cudaGetSymbolAddress((void**)&wprj, g_wprj);
    cudaGetSymbolAddress((void**)&wfc1, g_wfc1);
    cudaGetSymbolAddress((void**)&wfc2, g_wfc2);
    cudaGetSymbolAddress((void**)&inv,  g_inv);

    cudaFuncSetAttribute(gemm_mma<0, true,  false, true >,
        cudaFuncAttributeMaxDynamicSharedMemorySize, SMEMB);
    cudaFuncSetAttribute(gemm_mma<0, false, true,  false>,
        cudaFuncAttributeMaxDynamicSharedMemorySize, SMEMB);
    cudaFuncSetAttribute(gemm_mma<1, false, false, true >,
        cudaFuncAttributeMaxDynamicSharedMemorySize, SMEMB);
    cudaFuncSetAttribute(attn_tc,
        cudaFuncAttributeMaxDynamicSharedMemorySize, ASMB);

    cudaMemcpyAsync(out, x, sizeof(float) * (size_t)BN_ROWS * D,
                    cudaMemcpyDeviceToDevice, 0);                            // 1
    prep_kernel<<<(SZ_FC1 + 255) / 256, 256>>>(w_qkv, w_proj, w_fc1, w_fc2, pos); // 2

    dim3 gQKV(3 * D / BNm, BN_ROWS / BMm);
    dim3 gPRJ(D / BNm,     BN_ROWS / BMm);
    dim3 gFC1(DFF / BNm,   BN_ROWS / BMm);
    dim3 gFC2(D / BNm,     BN_ROWS / BMm);
    int lnBlocks = BN_ROWS / 8;

    for (int i = 0; i < 2; i++) {
        ln_kernel<<<lnBlocks, 256>>>(out, ln1_g + i * D, ln1_b + i * D, xn);  // 3
        gemm_mma<0, true, false, true><<<gQKV, 128, SMEMB>>>(                 // 4
            xn, wqkv + (size_t)i * D * 3 * D, b_qkv + i * 3 * D,
            nullptr, inv, qkv, D, 3 * D);
        attn_tc<<<BATCH * KC, 192, ASMB>>>(qkv, o);                           // 5 <- capture
        gemm_mma<0, false, true, false><<<gPRJ, 128, SMEMB>>>(
            o, wprj + (size_t)i * D * D, b_proj + i * D,
            out, nullptr, out, D, D);
        ln_kernel<<<lnBlocks, 256>>>(out, ln2_g + i * D, ln2_b + i * D, xn);
        gemm_mma<1, false, false, true><<<gFC1, 128, SMEMB>>>(
            xn, wfc1 + (size_t)i * D * DFF, b_fc1 + i * DFF,
            nullptr, nullptr, hbuf, D, DFF);
        gemm_mma<0, false, true, false><<<gFC2, 128, SMEMB>>>(
            hbuf, wfc2 + (size_t)i * DFF * D, b_fc2 + i * D,
            out, nullptr, out, DFF, D);
    }
}